// round 17
// baseline (speedup 1.0000x reference)
#include <cuda_runtime.h>
#include <cuda_bf16.h>

// Problem constants
#define BB   64
#define LL   32
#define NT   64
#define TT   64
#define SS   128
#define VV   50000
#define EMB  512
#define SD   512
#define EPSF 1e-9f
#define NCELL 528           // L*(L+1)/2 per batch
#define OMAX  1856          // max cells for levels >= 4
#define SCSTR (1984 * 64)   // score-partial slice stride (max cells = 1984)

// ----------------------------------------------------------------------------
// Persistent scratch (device globals)
// ----------------------------------------------------------------------------
__device__ float         g_chart_p[BB * NCELL * SS];    // 17 MB
__device__ float         g_u      [BB * NCELL * SS];    // 17 MB
__device__ float         g_chart_f[BB * NCELL * SD];    // 69 MB
__device__ float         g_T      [BB * NCELL * 1024];  // 138 MB  (Lt | Rt)
__device__ __nv_bfloat16 g_R1     [BB * LL * 4096];     // 17 MB  R1[c1][a*64+s]
__device__ __nv_bfloat16 g_R1L    [BB * LL * 8192];     // 33 MB  R1L[c1][a*128+t]
__device__ float         g_O      [OMAX * 4096];        // 30 MB  O[c][s*64+t]
__device__ float         g_scpart [9 * SCSTR];          // 4.6 MB score partials
__device__ float         g_GsumT  [2][64 * 128];        // GsumT[v][t][s]
// Pre-transposed bf16 B matrices for tensor-core GEMMs ([N][K] layout)
__device__ __nv_bfloat16 g_W2hT[1024 * 512];            // hi split of W2^T
__device__ __nv_bfloat16 g_W2lT[1024 * 512];            // lo split
__device__ __nv_bfloat16 g_G2t [64 * 4096];             // G2t[a][s*64+t]   (s,t<64)
__device__ __nv_bfloat16 g_GB1t[4096 * 64];             // GB1t[a*64+s][t]  = G[a,s,64+t]
__device__ __nv_bfloat16 g_GB2t[8192 * 64];             // GB2t[a*128+t][s] = G[a,64+s,t]

__host__ __device__ __forceinline__ int triOff(int len) {
    return ((len - 1) * (66 - len)) >> 1;
}
__device__ __forceinline__ int cellIdx(int b, int i, int len) {
    return b * NCELL + triOff(len) + i;
}

// ----------------------------------------------------------------------------
// Single fused prep kernel: gsum | w2t | g2t | gb1t | gb2t by block range
// ----------------------------------------------------------------------------
__global__ void prep_all(const float* __restrict__ G, const float* __restrict__ Wm) {
    int bid = blockIdx.x;
    int tid = threadIdx.x;
    if (bid < 64) {
        int idx = bid * 256 + tid;                      // 2*64*128
        int v = idx >> 13, t = (idx >> 7) & 63, s = idx & 127;
        const float* gp = G + s * 128 + v * 64 + t;
        float sum = 0.f;
        #pragma unroll 8
        for (int a = 0; a < 64; ++a) sum += gp[a * 16384];
        g_GsumT[v][t * 128 + s] = sum;
    } else if (bid < 2112) {
        int idx = (bid - 64) * 256 + tid;               // 1024*512
        int j = idx >> 9, k = idx & 511;
        float w = (j < 512) ? Wm[k * 512 + j] : Wm[(512 + k) * 512 + (j - 512)];
        __nv_bfloat16 h = __float2bfloat16(w);
        g_W2hT[idx] = h;
        g_W2lT[idx] = __float2bfloat16(w - __bfloat162float(h));
    } else if (bid < 3136) {
        int idx = (bid - 2112) * 256 + tid;             // 64*4096
        int a = idx >> 12, j = idx & 4095;
        int s = j >> 6, t = j & 63;
        g_G2t[idx] = __float2bfloat16(G[a * 16384 + s * 128 + t]);
    } else if (bid < 4160) {
        int idx = (bid - 3136) * 256 + tid;             // 4096*64
        int j = idx >> 6, t = idx & 63;
        int a = j >> 6, s = j & 63;
        g_GB1t[idx] = __float2bfloat16(G[a * 16384 + s * 128 + 64 + t]);
    } else {
        int idx = (bid - 4160) * 256 + tid;             // 8192*64
        int j = idx >> 6, s = idx & 63;
        int a = j >> 7, t = j & 127;
        g_GB2t[idx] = __float2bfloat16(G[a * 16384 + (64 + s) * 128 + t]);
    }
}

// ----------------------------------------------------------------------------
// Level-1: preterminal distribution + u1 epilogue (fused)
// ----------------------------------------------------------------------------
__global__ void diag_kernel(const int* __restrict__ word,
                            const float* __restrict__ preterm) {
    int c = blockIdx.x;                  // b*32+i
    int tid = threadIdx.x;               // 128 threads
    int w = word[c];
    __shared__ float ps[64], red2[2];
    float v = 0.f;
    if (tid < 64) {
        v = preterm[tid * VV + w];
        float s = v;
        #pragma unroll
        for (int o = 16; o; o >>= 1) s += __shfl_down_sync(0xffffffffu, s, o);
        if ((tid & 31) == 0) red2[tid >> 5] = s;
    }
    __syncthreads();
    float tot = red2[0] + red2[1] + EPSF;
    int b = c >> 5, i = c & 31;
    long cb = (long)cellIdx(b, i, 1) * SS;
    if (tid < 64) {
        float pv = v / tot;
        g_chart_p[cb + tid]      = 0.f;
        g_chart_p[cb + 64 + tid] = pv;
        ps[tid] = pv;
    }
    __syncthreads();
    const float* gs = g_GsumT[1] + tid;
    float u = 0.f;
    #pragma unroll 8
    for (int t = 0; t < 64; ++t) u += gs[t * 128] * ps[t];
    g_u[cb + tid] = u;
}

// ----------------------------------------------------------------------------
// Scalar tiled GEMM (feat gather-GEMM only)
// ----------------------------------------------------------------------------
__global__ void __launch_bounds__(256) gemm_k(
    const float* __restrict__ A, const float* __restrict__ Bm,
    float* __restrict__ C, int K, int N, int n,
    const int* __restrict__ gidx,
    long c_bs, int c_is, int c_cst,
    const float* __restrict__ bias)
{
    __shared__ float As[16][64];
    __shared__ float Bs[16][64];
    int tid  = threadIdx.x;
    int row0 = blockIdx.y << 6, col0 = blockIdx.x << 6;

    int lr = tid >> 2, lk4 = (tid & 3) << 2;
    const float* Aptr = A + (long)gidx[row0 + lr] * EMB + lk4;
    int bk = tid >> 4, bn4 = (tid & 15) << 2;
    const float* Bptr = Bm + (long)bk * N + col0 + bn4;

    int ty = tid >> 4, tx = tid & 15;
    float acc[4][4];
    #pragma unroll
    for (int ii = 0; ii < 4; ++ii)
        #pragma unroll
        for (int jj = 0; jj < 4; ++jj) acc[ii][jj] = 0.f;

    for (int k0 = 0; k0 < K; k0 += 16) {
        float4 av = *(const float4*)(Aptr + k0);
        float4 bv = *(const float4*)(Bptr + (long)k0 * N);
        if (k0) __syncthreads();
        As[lk4 + 0][lr] = av.x; As[lk4 + 1][lr] = av.y;
        As[lk4 + 2][lr] = av.z; As[lk4 + 3][lr] = av.w;
        *(float4*)&Bs[bk][bn4] = bv;
        __syncthreads();
        #pragma unroll
        for (int kk = 0; kk < 16; ++kk) {
            float4 af = *(const float4*)&As[kk][ty << 2];
            float4 bf = *(const float4*)&Bs[kk][tx << 2];
            float ar[4] = {af.x, af.y, af.z, af.w};
            float br[4] = {bf.x, bf.y, bf.z, bf.w};
            #pragma unroll
            for (int ii = 0; ii < 4; ++ii)
                #pragma unroll
                for (int jj = 0; jj < 4; ++jj)
                    acc[ii][jj] += ar[ii] * br[jj];
        }
    }

    int cc = col0 + (tx << 2);
    #pragma unroll
    for (int ii = 0; ii < 4; ++ii) {
        int rr = row0 + (ty << 2) + ii;
        int b = rr / n, i = rr - b * n;
        long base = (long)b * c_bs + (long)i * c_is + c_cst + cc;
        float v0 = fmaxf(acc[ii][0] + bias[cc + 0], 0.f);
        float v1 = fmaxf(acc[ii][1] + bias[cc + 1], 0.f);
        float v2 = fmaxf(acc[ii][2] + bias[cc + 2], 0.f);
        float v3 = fmaxf(acc[ii][3] + bias[cc + 3], 0.f);
        *(float4*)(C + base) = make_float4(v0, v1, v2, v3);
    }
}

// ----------------------------------------------------------------------------
// Tensor-core GEMM machinery
// ----------------------------------------------------------------------------
__device__ __forceinline__ void mma_bf16(float* d,
        unsigned a0, unsigned a1, unsigned a2, unsigned a3,
        unsigned b0, unsigned b1) {
    asm volatile(
        "mma.sync.aligned.m16n8k16.row.col.f32.bf16.bf16.f32 "
        "{%0,%1,%2,%3}, {%4,%5,%6,%7}, {%8,%9}, {%0,%1,%2,%3};"
        : "+f"(d[0]), "+f"(d[1]), "+f"(d[2]), "+f"(d[3])
        : "r"(a0), "r"(a1), "r"(a2), "r"(a3), "r"(b0), "r"(b1));
}

__device__ __forceinline__ void ldsm_x4(unsigned* r, unsigned addr) {
    asm volatile("ldmatrix.sync.aligned.m8n8.x4.shared.b16 {%0,%1,%2,%3}, [%4];"
        : "=r"(r[0]), "=r"(r[1]), "=r"(r[2]), "=r"(r[3]) : "r"(addr));
}

#define TPAD 40   // smem row stride in bf16 (80B, ldmatrix-aligned, conflict-free)
#define GT_SMEM (2 * (64 * TPAD + 64 * TPAD + 128 * TPAD + 128 * TPAD))  // 30720 B

// Main 64x128 tile body: C[r][j] = sum_k A[r][k]*Bt[j][k], A fp32->bf16(+split)
template<int SPLIT, int OBF16>
__device__ __forceinline__ void gemm_t_body(
    char* smbase, int bx, int by,
    const float* __restrict__ A,
    const __nv_bfloat16* __restrict__ Bh,
    const __nv_bfloat16* __restrict__ Bl,
    void* __restrict__ C, int K, int N, int n,
    int a_bs, int a_is, int a_cst,
    long c_bs, int c_is, int c_cst)
{
    typedef __nv_bfloat16 bf;
    bf (*Ash)[TPAD] = (bf(*)[TPAD])(smbase);
    bf (*Asl)[TPAD] = (bf(*)[TPAD])(smbase + 5120);
    bf (*Bsh)[TPAD] = (bf(*)[TPAD])(smbase + 10240);
    bf (*Bsl)[TPAD] = (bf(*)[TPAD])(smbase + 20480);

    int tid  = threadIdx.x;
    int row0 = by << 6, col0 = bx << 7;

    int ar = tid >> 2, aq = tid & 3;
    {
        int r = row0 + ar;
        int b = r / n, i = r - b * n;
        A += (long)b * a_bs + (long)i * a_is + a_cst + aq * 8;
    }
    int brow = tid >> 1, bq = tid & 1;
    const bf* Bhp = Bh + (long)(col0 + brow) * K + bq * 16;
    const bf* Blp = SPLIT ? (Bl + (long)(col0 + brow) * K + bq * 16) : Bh;

    int w = tid >> 5, lane = tid & 31;
    int m0 = (w >> 2) << 5, n0 = (w & 3) << 5;
    int g = lane >> 2, cq = lane & 3;

    unsigned smA = (unsigned)__cvta_generic_to_shared(smbase);
    unsigned aRow = lane & 15, aCol = (unsigned)((lane >> 4) << 3);
    unsigned aOffH0 = smA + ((m0 + aRow) * TPAD + aCol) * 2;
    unsigned aOffH1 = aOffH0 + 16 * TPAD * 2;
    unsigned aOffL0 = aOffH0 + 5120, aOffL1 = aOffH1 + 5120;
    unsigned bRow = (unsigned)(((lane >> 4) << 3) + (lane & 7));
    unsigned bCol = (unsigned)(((lane >> 3) & 1) << 3);
    unsigned bOffH0 = smA + 10240 + ((n0 + bRow) * TPAD + bCol) * 2;
    unsigned bOffH1 = bOffH0 + 16 * TPAD * 2;
    unsigned bOffL0 = bOffH0 + 10240, bOffL1 = bOffH1 + 10240;

    float acc[2][4][4];
    #pragma unroll
    for (int mt = 0; mt < 2; ++mt)
        #pragma unroll
        for (int nt = 0; nt < 4; ++nt)
            #pragma unroll
            for (int e = 0; e < 4; ++e) acc[mt][nt][e] = 0.f;

    for (int k0 = 0; k0 < K; k0 += 32) {
        float4 av0 = *(const float4*)(A + k0);
        float4 av1 = *(const float4*)(A + k0 + 4);
        uint4 bh0 = *(const uint4*)(Bhp + k0);
        uint4 bh1 = *(const uint4*)(Bhp + k0 + 8);
        uint4 bl0, bl1;
        if (SPLIT) {
            bl0 = *(const uint4*)(Blp + k0);
            bl1 = *(const uint4*)(Blp + k0 + 8);
        }
        if (k0) __syncthreads();
        {
            float f[8] = {av0.x, av0.y, av0.z, av0.w, av1.x, av1.y, av1.z, av1.w};
            #pragma unroll
            for (int j = 0; j < 8; j += 2) {
                __nv_bfloat16 h0 = __float2bfloat16(f[j]);
                __nv_bfloat16 h1 = __float2bfloat16(f[j + 1]);
                *(__nv_bfloat162*)&Ash[ar][aq * 8 + j] = __nv_bfloat162(h0, h1);
                if (SPLIT) {
                    __nv_bfloat16 l0 = __float2bfloat16(f[j]     - __bfloat162float(h0));
                    __nv_bfloat16 l1 = __float2bfloat16(f[j + 1] - __bfloat162float(h1));
                    *(__nv_bfloat162*)&Asl[ar][aq * 8 + j] = __nv_bfloat162(l0, l1);
                }
            }
            *(uint4*)&Bsh[brow][bq * 16]     = bh0;
            *(uint4*)&Bsh[brow][bq * 16 + 8] = bh1;
            if (SPLIT) {
                *(uint4*)&Bsl[brow][bq * 16]     = bl0;
                *(uint4*)&Bsl[brow][bq * 16 + 8] = bl1;
            }
        }
        __syncthreads();

        #pragma unroll
        for (int ks = 0; ks < 2; ++ks) {
            unsigned kby = (unsigned)(ks << 5);
            unsigned ah[2][4], al[2][4];
            ldsm_x4(ah[0], aOffH0 + kby);
            ldsm_x4(ah[1], aOffH1 + kby);
            if (SPLIT) {
                ldsm_x4(al[0], aOffL0 + kby);
                ldsm_x4(al[1], aOffL1 + kby);
            }
            unsigned bhf[2][4], blf[2][4];
            ldsm_x4(bhf[0], bOffH0 + kby);
            ldsm_x4(bhf[1], bOffH1 + kby);
            if (SPLIT) {
                ldsm_x4(blf[0], bOffL0 + kby);
                ldsm_x4(blf[1], bOffL1 + kby);
            }
            #pragma unroll
            for (int nt = 0; nt < 4; ++nt) {
                int j = nt >> 1, h = (nt & 1) << 1;
                unsigned b0 = bhf[j][h], b1 = bhf[j][h + 1];
                #pragma unroll
                for (int mt = 0; mt < 2; ++mt) {
                    mma_bf16(acc[mt][nt], ah[mt][0], ah[mt][1], ah[mt][2], ah[mt][3], b0, b1);
                    if (SPLIT)
                        mma_bf16(acc[mt][nt], al[mt][0], al[mt][1], al[mt][2], al[mt][3], b0, b1);
                }
                if (SPLIT) {
                    unsigned c0 = blf[j][h], c1 = blf[j][h + 1];
                    #pragma unroll
                    for (int mt = 0; mt < 2; ++mt)
                        mma_bf16(acc[mt][nt], ah[mt][0], ah[mt][1], ah[mt][2], ah[mt][3], c0, c1);
                }
            }
        }
    }

    #pragma unroll
    for (int mt = 0; mt < 2; ++mt) {
        #pragma unroll
        for (int h2 = 0; h2 < 2; ++h2) {
            int rr = row0 + m0 + (mt << 4) + g + (h2 << 3);
            int b = rr / n, i = rr - b * n;
            long base = (long)b * c_bs + (long)i * c_is + c_cst;
            #pragma unroll
            for (int nt = 0; nt < 4; ++nt) {
                int cc = col0 + n0 + (nt << 3) + 2 * cq;
                float v0 = acc[mt][nt][h2 * 2 + 0];
                float v1 = acc[mt][nt][h2 * 2 + 1];
                if (OBF16) {
                    __nv_bfloat162 hv = __floats2bfloat162_rn(v0, v1);
                    *(unsigned*)((__nv_bfloat16*)C + base + cc) = *(unsigned*)&hv;
                } else {
                    *(float2*)((float*)C + base + cc) = make_float2(v0, v1);
                }
            }
        }
    }
}

// ----------------------------------------------------------------------------
// scmid body: split-K score contraction.
// Block (kc, by): scpart[1+kc][c][a] = sum_{k in chunk kc} O[c][k]*G2t[a][k]
// 64 rows x 64 cols, K-chunk = 512. Warps: 2(m) x 4(n of 16).
// ----------------------------------------------------------------------------
__device__ __forceinline__ void scmid_body(
    char* smbase, int kc, int by,
    const float* __restrict__ O, const __nv_bfloat16* __restrict__ G2t,
    float* __restrict__ outP)
{
    typedef __nv_bfloat16 bf;
    bf (*Ash)[TPAD] = (bf(*)[TPAD])(smbase);
    bf (*Bsh)[TPAD] = (bf(*)[TPAD])(smbase + 5120);

    int tid = threadIdx.x;
    int row0 = by << 6;

    int ar = tid >> 2, aq = tid & 3;
    const float* Ap = O + (long)(row0 + ar) * 4096 + kc * 512 + aq * 8;
    int brow = tid >> 2, bq8 = (tid & 3) << 3;
    const bf* Bp = G2t + (long)brow * 4096 + kc * 512 + bq8;

    int w = tid >> 5, lane = tid & 31;
    int m0 = (w >> 2) << 5, n0 = (w & 3) << 4;
    int g = lane >> 2, cq = lane & 3;

    unsigned smA = (unsigned)__cvta_generic_to_shared(smbase);
    unsigned aOffH0 = smA + ((m0 + (lane & 15)) * TPAD + ((lane >> 4) << 3)) * 2;
    unsigned aOffH1 = aOffH0 + 16 * TPAD * 2;
    unsigned bRow = (unsigned)(((lane >> 4) << 3) + (lane & 7));
    unsigned bCol = (unsigned)(((lane >> 3) & 1) << 3);
    unsigned bOff = smA + 5120 + ((n0 + bRow) * TPAD + bCol) * 2;

    float acc[2][2][4];
    #pragma unroll
    for (int mt = 0; mt < 2; ++mt)
        #pragma unroll
        for (int nt = 0; nt < 2; ++nt)
            #pragma unroll
            for (int e = 0; e < 4; ++e) acc[mt][nt][e] = 0.f;

    for (int k0 = 0; k0 < 512; k0 += 32) {
        float4 av0 = *(const float4*)(Ap + k0);
        float4 av1 = *(const float4*)(Ap + k0 + 4);
        uint4 bv = *(const uint4*)(Bp + k0);        // 8 bf16
        if (k0) __syncthreads();
        {
            float f[8] = {av0.x, av0.y, av0.z, av0.w, av1.x, av1.y, av1.z, av1.w};
            #pragma unroll
            for (int j = 0; j < 8; j += 2) {
                *(__nv_bfloat162*)&Ash[ar][aq * 8 + j] =
                    __floats2bfloat162_rn(f[j], f[j + 1]);
            }
            *(uint4*)&Bsh[brow][bq8] = bv;
        }
        __syncthreads();
        #pragma unroll
        for (int ks = 0; ks < 2; ++ks) {
            unsigned kby = (unsigned)(ks << 5);
            unsigned ah0[4], ah1[4], bf4[4];
            ldsm_x4(ah0, aOffH0 + kby);
            ldsm_x4(ah1, aOffH1 + kby);
            ldsm_x4(bf4, bOff + kby);
            #pragma unroll
            for (int nt = 0; nt < 2; ++nt) {
                unsigned b0 = bf4[nt * 2], b1 = bf4[nt * 2 + 1];
                mma_bf16(acc[0][nt], ah0[0], ah0[1], ah0[2], ah0[3], b0, b1);
                mma_bf16(acc[1][nt], ah1[0], ah1[1], ah1[2], ah1[3], b0, b1);
            }
        }
    }

    float* dst = outP + (long)(1 + kc) * SCSTR;
    #pragma unroll
    for (int mt = 0; mt < 2; ++mt)
        #pragma unroll
        for (int h2 = 0; h2 < 2; ++h2) {
            int rr = row0 + m0 + (mt << 4) + g + (h2 << 3);
            #pragma unroll
            for (int nt = 0; nt < 2; ++nt) {
                int cc = n0 + (nt << 3) + 2 * cq;
                *(float2*)(dst + (long)rr * 64 + cc) =
                    make_float2(acc[mt][nt][h2 * 2], acc[mt][nt][h2 * 2 + 1]);
            }
        }
}

// ----------------------------------------------------------------------------
// Fused GEMM dispatcher:
//   [0,nT):           T tiles       (reads f of this level)
//   [nT,nT+nM):       scmid tiles   (reads O of this level)
//   [.., +nR1):       R1 tiles      (level 1 only)
//   [.., rest):       R1L tiles     (level 1 only)
// ----------------------------------------------------------------------------
__global__ void __launch_bounds__(256) level_gemms(
    const float* __restrict__ P, const float* __restrict__ F,
    const __nv_bfloat16* __restrict__ W2h, const __nv_bfloat16* __restrict__ W2l,
    const __nv_bfloat16* __restrict__ G2t,
    const __nv_bfloat16* __restrict__ GB1t, const __nv_bfloat16* __restrict__ GB2t,
    const float* __restrict__ O, float* __restrict__ scpart,
    float* __restrict__ T, __nv_bfloat16* __restrict__ R1, __nv_bfloat16* __restrict__ R1L,
    int n, int nT, int nM, int nR1,
    int aP_cst, int aF_cst, int cT_cst)
{
    extern __shared__ char sm[];
    int bid = blockIdx.x;
    if (bid < nT) {
        gemm_t_body<1, 0>(sm, bid & 7, bid >> 3, F, W2h, W2l, T, 512, 1024, n,
                          NCELL * SD, SD, aF_cst, (long)NCELL * 1024, 1024, cT_cst);
    } else if (bid < nT + nM) {
        int r = bid - nT;
        scmid_body(sm, r & 7, r >> 3, O, G2t, scpart);
    } else if (bid < nT + nM + nR1) {
        int r = bid - nT - nM;
        gemm_t_body<0, 1>(sm, r & 31, r >> 5, P, GB1t, nullptr, R1, 64, 4096, n,
                          NCELL * SS, SS, aP_cst, (long)LL * 4096, 4096, 0);
    } else {
        int r = bid - nT - nM - nR1;
        gemm_t_body<0, 1>(sm, r & 63, r >> 6, P, GB2t, nullptr, R1L, 64, 8192, n,
                          NCELL * SS, SS, aP_cst, (long)LL * 8192, 8192, 0);
    }
}

// ----------------------------------------------------------------------------
// Per-level kernel: pipelined split loop.
//   d==1:      boundary score via R1L[left] dot rp
//   d==ln-1:   boundary score via R1[right] dot lp  (rLen==1, d>=2)
//   else:      O[s][t] += lp[s]*rp[t]   (registers)
// masses + lagged combine; writes scpart slice 0, f, O.
// ----------------------------------------------------------------------------
__device__ __forceinline__ float dot16v(uint4 v0, uint4 v1, const float* s) {
    const unsigned* u0 = (const unsigned*)&v0;
    const unsigned* u1 = (const unsigned*)&v1;
    float acc = 0.f;
    #pragma unroll
    for (int w = 0; w < 4; ++w) {
        float2 f0 = __bfloat1622float2(*(const __nv_bfloat162*)&u0[w]);
        float2 f1 = __bfloat1622float2(*(const __nv_bfloat162*)&u1[w]);
        acc += f0.x * s[2 * w]     + f0.y * s[2 * w + 1]
             + f1.x * s[8 + 2 * w] + f1.y * s[8 + 2 * w + 1];
    }
    return acc;
}

__global__ void __launch_bounds__(256) level_kernel(int ln, int n,
                                                    const float* __restrict__ bm) {
    int c = blockIdx.x;
    int b = c / n, i = c - b * n;
    int tid = threadIdx.x;
    int a = tid >> 2, q = tid & 3;      // also s = a for O accumulation
    int t0 = q << 4;
    __shared__ float lp[64], rp[64], us[64], sc[64];
    __shared__ float mp0[32], mp1[32];
    float acc = 0.f;
    float Oacc[16];
    #pragma unroll
    for (int j = 0; j < 16; ++j) Oacc[j] = 0.f;
    float2 facc = make_float2(0.f, 0.f);
    float mtot = 0.f;
    float2 bmv = *(const float2*)(bm + 2 * tid);

    // ---- prologue: 2-deep operand stage + boundary R rows ----
    float s_cur = 0.f, s_nxt = 0.f;
    {
        int rLen = ln - 1;
        int soff_r = (rLen == 1) ? 64 : 0;
        if (tid < 64)
            s_cur = g_chart_p[(long)cellIdx(b, i, 1) * SS + 64 + tid];
        else if (tid < 128)
            s_cur = g_u[(long)cellIdx(b, i + 1, rLen) * SS + 64 + (tid - 64)];
        else if (tid < 192)
            s_cur = g_chart_p[(long)cellIdx(b, i + 1, rLen) * SS + soff_r + (tid - 128)];
    }
    if (ln > 2) {
        int rLn = ln - 2;
        int soff_r = (rLn == 1) ? 64 : 0;
        if (tid < 64)
            s_nxt = g_chart_p[(long)cellIdx(b, i, 2) * SS + tid];
        else if (tid < 128)
            s_nxt = g_u[(long)cellIdx(b, i + 2, rLn) * SS + (tid - 64)];
        else if (tid < 192)
            s_nxt = g_chart_p[(long)cellIdx(b, i + 2, rLn) * SS + soff_r + (tid - 128)];
    }
    uint4 rA0, rA1;
    {
        int rLen = ln - 1;
        int soff_r = (rLen == 1) ? 64 : 0;
        const __nv_bfloat16* rP = g_R1L + ((long)(b * LL + i)) * 8192
                                        + a * 128 + soff_r + t0;
        rA0 = __ldcs((const uint4*)rP);
        rA1 = __ldcs((const uint4*)(rP + 8));
    }
    uint4 rB0 = make_uint4(0,0,0,0), rB1 = rB0;
    if (ln >= 3) {
        const __nv_bfloat16* rP = g_R1 + ((long)(b * LL + i + ln - 1)) * 4096
                                       + a * 64 + t0;
        rB0 = __ldcs((const uint4*)rP);
        rB1 = __ldcs((const uint4*)(rP + 8));
    }
    float2 tl = make_float2(0.f, 0.f), tr = make_float2(0.f, 0.f);

    for (int d = 1; d < ln; ++d) {
        __syncthreads();                       // prior compute done; mp[d-2] visible
        if (d > 1) {
            float m = mp0[d - 2] + mp1[d - 2];
            mtot += m;
            facc.x += m * fmaxf(tl.x + tr.x + bmv.x, 0.f);
            facc.y += m * fmaxf(tl.y + tr.y + bmv.y, 0.f);
        }
        if (tid < 64)       lp[tid] = s_cur;
        else if (tid < 128) us[tid - 64] = s_cur;
        else if (tid < 192) rp[tid - 128] = s_cur;
        __syncthreads();

        // advance operand pipeline: fetch split d+2
        s_cur = s_nxt;
        if (d + 2 < ln) {
            int dn = d + 2, rLn = ln - dn;
            int soff_rn = (rLn == 1) ? 64 : 0;
            if (tid < 64)
                s_nxt = g_chart_p[(long)cellIdx(b, i, dn) * SS + tid];
            else if (tid < 128)
                s_nxt = g_u[(long)cellIdx(b, i + dn, rLn) * SS + (tid - 64)];
            else if (tid < 192)
                s_nxt = g_chart_p[(long)cellIdx(b, i + dn, rLn) * SS + soff_rn + (tid - 128)];
        }
        // T rows for this split (combined next iteration)
        {
            const float* TLp = g_T + (long)cellIdx(b, i, d) * 1024;
            const float* TRp = g_T + (long)cellIdx(b, i + d, ln - d) * 1024 + 512;
            tl = __ldcs((const float2*)(TLp + 2 * tid));
            tr = __ldcs((const float2*)(TRp + 2 * tid));
        }

        // mass_d partials (warps 0,1)
        if (tid < 64) {
            float m = lp[tid] * us[tid];
            #pragma unroll
            for (int o = 16; o; o >>= 1) m += __shfl_down_sync(0xffffffffu, m, o);
            if (tid == 0)       mp0[d - 1] = m;
            else if (tid == 32) mp1[d - 1] = m;
        }

        // score contribution
        if (d == 1) {
            acc += dot16v(rA0, rA1, rp + t0);
        } else if (d == ln - 1) {              // rLen == 1, d >= 2
            acc += dot16v(rB0, rB1, lp + t0);
        } else {
            float l = lp[a];
            #pragma unroll
            for (int j = 0; j < 16; ++j) Oacc[j] += l * rp[t0 + j];
        }
    }

    int D = ln - 1;
    __syncthreads();                           // mp for split D visible
    {
        float m = mp0[D - 1] + mp1[D - 1];
        mtot += m;
        facc.x += m * fmaxf(tl.x + tr.x + bmv.x, 0.f);
        facc.y += m * fmaxf(tl.y + tr.y + bmv.y, 0.f);
    }

    // reduce boundary scores over q -> scpart slice 0
    acc += __shfl_down_sync(0xffffffffu, acc, 2);
    acc += __shfl_down_sync(0xffffffffu, acc, 1);
    if (q == 0) sc[a] = acc;
    __syncthreads();
    if (tid < 64) g_scpart[(long)c * 64 + tid] = sc[tid];

    // write O for the mid-score GEMM (ln >= 4)
    if (ln >= 4) {
        float* Orow = g_O + (long)c * 4096 + a * 64 + t0;
        ((float4*)Orow)[0] = make_float4(Oacc[0],  Oacc[1],  Oacc[2],  Oacc[3]);
        ((float4*)Orow)[1] = make_float4(Oacc[4],  Oacc[5],  Oacc[6],  Oacc[7]);
        ((float4*)Orow)[2] = make_float4(Oacc[8],  Oacc[9],  Oacc[10], Oacc[11]);
        ((float4*)Orow)[3] = make_float4(Oacc[12], Oacc[13], Oacc[14], Oacc[15]);
    }

    // write f = facc / (mtot + eps)
    float inv = 1.f / (mtot + EPSF);
    *(float2*)(g_chart_f + (long)cellIdx(b, i, ln) * SD + 2 * tid) =
        make_float2(facc.x * inv, facc.y * inv);
}

// ----------------------------------------------------------------------------
// Norm kernel: p = (sum of score partials) / total; u = GsumT . p
// ----------------------------------------------------------------------------
__global__ void norm_kernel(int ln, int n, int np, int computeU) {
    int c = blockIdx.x;
    int b = c / n, i = c - b * n;
    int tid = threadIdx.x;               // 128 threads
    __shared__ float ps[64], red[2];
    float v = 0.f;
    if (tid < 64) {
        for (int p = 0; p < np; ++p)
            v += g_scpart[(long)p * SCSTR + (long)c * 64 + tid];
        float s = v;
        #pragma unroll
        for (int o = 16; o; o >>= 1) s += __shfl_down_sync(0xffffffffu, s, o);
        if ((tid & 31) == 0) red[tid >> 5] = s;
    }
    __syncthreads();
    float tot = red[0] + red[1] + EPSF;
    if (tid < 64) {
        float pv = v / tot;
        g_chart_p[(long)cellIdx(b, i, ln) * SS + tid] = pv;
        ps[tid] = pv;
    }
    if (computeU) {
        __syncthreads();
        const float* gs = g_GsumT[0] + tid;
        float u = 0.f;
        #pragma unroll 8
        for (int t = 0; t < 64; ++t) u += gs[t * 128] * ps[t];
        g_u[(long)cellIdx(b, i, ln) * SS + tid] = u;
    }
}

// ----------------------------------------------------------------------------
// Root
// ----------------------------------------------------------------------------
__global__ void root_kernel(const float* __restrict__ starts, float* __restrict__ out) {
    int b = blockIdx.x, tid = threadIdx.x;  // 128 threads
    const float* p = g_chart_p + (long)cellIdx(b, 0, LL) * SS;
    float v = p[tid] * starts[tid];
    #pragma unroll
    for (int o = 16; o; o >>= 1) v += __shfl_down_sync(0xffffffffu, v, o);
    __shared__ float red[4];
    if ((tid & 31) == 0) red[tid >> 5] = v;
    __syncthreads();
    float score = red[0] + red[1] + red[2] + red[3];
    const float* f = g_chart_f + (long)cellIdx(b, 0, LL) * SD;
    for (int h = tid; h < SD; h += 128) out[b * SD + h] = f[h] * score;
}

// ----------------------------------------------------------------------------
// Host driver
// ----------------------------------------------------------------------------
extern "C" void kernel_launch(void* const* d_in, const int* in_sizes, int n_in,
                              void* d_out, int out_size) {
    const int*   word    = (const int*)  d_in[0];
    const float* emb     = (const float*)d_in[1];
    const float* preterm = (const float*)d_in[2];
    const float* G       = (const float*)d_in[3];
    const float* starts  = (const float*)d_in[4];
    const float* Wp      = (const float*)d_in[5];
    const float* bp      = (const float*)d_in[6];
    const float* Wm      = (const float*)d_in[7];
    const float* bm      = (const float*)d_in[8];
    float* out = (float*)d_out;

    float *pP, *pF, *pT, *pO, *pSc;
    __nv_bfloat16 *pR1, *pR1L, *pW2h, *pW2l, *pG2t, *pGB1t, *pGB2t;
    cudaGetSymbolAddress((void**)&pP,    g_chart_p);
    cudaGetSymbolAddress((void**)&pF,    g_chart_f);
    cudaGetSymbolAddress((void**)&pT,    g_T);
    cudaGetSymbolAddress((void**)&pO,    g_O);
    cudaGetSymbolAddress((void**)&pSc,   g_scpart);
    cudaGetSymbolAddress((void**)&pR1,   g_R1);
    cudaGetSymbolAddress((void**)&pR1L,  g_R1L);
    cudaGetSymbolAddress((void**)&pW2h,  g_W2hT);
    cudaGetSymbolAddress((void**)&pW2l,  g_W2lT);
    cudaGetSymbolAddress((void**)&pG2t,  g_G2t);
    cudaGetSymbolAddress((void**)&pGB1t, g_GB1t);
    cudaGetSymbolAddress((void**)&pGB2t, g_GB2t);

    // Prep (single launch)
    prep_all<<<6208, 256>>>(G, Wm);

    // Level 1: p + u1 fused
    diag_kernel<<<BB * LL, 128>>>(word, preterm);

    {
        int rows = BB * LL;   // 2048
        // feat0 = relu(emb[word] @ Wp + bp)
        dim3 gF(SD >> 6, rows >> 6);
        gemm_k<<<gF, 256>>>(emb, Wp, pF, EMB, SD, LL, word,
                            (long)NCELL * SD, SD, triOff(1) * SD, bp);
        // Fused T(1) + R1 + R1L (one launch)
        int nT = (rows >> 6) * 8;        // 256
        int nR1 = (rows >> 6) * 32;      // 1024
        int nR1L = (rows >> 6) * 64;     // 2048
        level_gemms<<<nT + nR1 + nR1L, 256, GT_SMEM>>>(
            pP, pF, pW2h, pW2l, pG2t, pGB1t, pGB2t,
            pO, pSc, pT, pR1, pR1L,
            LL, nT, 0, nR1,
            triOff(1) * SS + 64, triOff(1) * SD, triOff(1) * 1024);
    }

    // Levels 2..32
    for (int ln = 2; ln <= LL; ++ln) {
        int nn = LL - ln + 1;
        int cells = BB * nn;
        level_kernel<<<cells, 256>>>(ln, nn, bm);
        int nT = (ln < LL) ? nn * 8 : 0;
        int nM = (ln >= 4) ? nn * 8 : 0;
        if (nT + nM)
            level_gemms<<<nT + nM, 256, GT_SMEM>>>(
                pP, pF, pW2h, pW2l, pG2t, pGB1t, pGB2t,
                pO, pSc, pT, pR1, pR1L,
                nn, nT, nM, 0,
                0, triOff(ln) * SD, triOff(ln) * 1024);
        int np = (ln >= 4) ? 9 : 1;
        norm_kernel<<<cells, 128>>>(ln, nn, np, (ln < LL) ? 1 : 0);
    }

    // Root
    root_kernel<<<BB, 128>>>(starts, out);
}